// round 14
// baseline (speedup 1.0000x reference)
#include <cuda_runtime.h>
#include <cuda_fp16.h>
#include <cstdint>

// B=16384, N=64, D=64, O=64
// softmax(others@a2 + robot@a1) == softmax(others@a2)  (robot term constant)
// out = elu( diag(1,attn) @ (h@W) )   -- attn folded into the epilogue
// 128-thread dedup mapping (warp = m-tile x all 64 cols), fp16 m16n8k16.
// XOR-swizzled smem h buffers (no padding, 16KB each, slot = quad^((row&1)<<2)),
// triple-buffered depth-2 cp.async. Register diet (<=128) for 4 CTAs/SM:
// A-frags converted to half2 per-q, vv from smem, GEMM split into 2 nt-halves.

#define GB 8      // batches per CTA
#define NBUF 3

#define SMEM_FLOATS (NBUF * 64 * 64 + 2 * 64 + 64)

__device__ __forceinline__ unsigned h2u(__half2 h) {
    return *reinterpret_cast<unsigned*>(&h);
}

__device__ __forceinline__ float elu1(float x) {
    return x > 0.f ? x : (__expf(x) - 1.f);
}

__device__ __forceinline__ void cp_async16(uint32_t saddr, const void* gptr) {
    asm volatile("cp.async.cg.shared.global [%0], [%1], 16;\n"
                 :: "r"(saddr), "l"(gptr));
}

__global__ __launch_bounds__(128, 4)
void gat_fused_kernel(const float* __restrict__ h,
                      const float* __restrict__ W,
                      const float* __restrict__ a,
                      float* __restrict__ out) {
    extern __shared__ float smem[];
    float* shbase = smem;                       // [NBUF][64*64], swizzled
    float* sdots  = smem + NBUF * 64 * 64;      // [2][64]
    float* sv2    = sdots + 128;                // [64], 16B-aligned

    const int tid  = threadIdx.x;
    const int lane = tid & 31;
    const int warp = tid >> 5;     // 0..3 = m-tile
    const int gid  = lane >> 2;    // 0..7
    const int tig  = lane & 3;     // 0..3
    const int swz  = (gid & 1) << 2;   // row-parity XOR for reads (rA,rB same parity)

    // ---- B-fragments (fp16) into registers, once ----
    // K-perm within slab q: actual col 16q+4t+j <-> mma-k {2t,2t+1,2t+8,2t+9}
    // N-perm: tile nt, local n -> col (nt>>1)*16 + (n>>1)*4 + (nt&1)*2 + (n&1)
    unsigned bfr[4][8][2];
#pragma unroll
    for (int q = 0; q < 4; ++q) {
        const int kr = 16 * q + 4 * tig;
#pragma unroll
        for (int nt = 0; nt < 8; ++nt) {
            int col = (nt >> 1) * 16 + (gid >> 1) * 4 + (nt & 1) * 2 + (gid & 1);
            bfr[q][nt][0] = h2u(__floats2half2_rn(W[kr * 64 + col],
                                                  W[(kr + 1) * 64 + col]));
            bfr[q][nt][1] = h2u(__floats2half2_rn(W[(kr + 2) * 64 + col],
                                                  W[(kr + 3) * 64 + col]));
        }
    }

    // ---- v2 = W @ a2 (threads 0..63) ----
    if (tid < 64) {
        const float* a2 = a + 64;
        float s = 0.f;
#pragma unroll
        for (int o = 0; o < 64; ++o) s = fmaf(W[tid * 64 + o], a2[o], s);
        sv2[tid] = s;
    }

    const size_t base = (size_t)blockIdx.x * GB * 4096;
    const int rA = warp * 16 + gid;   // this thread's two rows
    const int rB = rA + 8;

    // ---- prefetch batches 0,1 (swizzled stores) ----
#pragma unroll
    for (int p = 0; p < 2; ++p) {
        const float* hb = h + base + (size_t)p * 4096;
        uint32_t sb = (uint32_t)__cvta_generic_to_shared(&shbase[p * 4096]);
#pragma unroll
        for (int c = tid; c < 1024; c += 128) {
            int row = c >> 4, q = c & 15;
            int slot = q ^ ((row & 1) << 2);
            cp_async16(sb + row * 256 + slot * 16, hb + c * 4);
        }
        asm volatile("cp.async.commit_group;\n");
    }

    for (int g = 0; g < GB; ++g) {
        if (g < GB - 1)
            asm volatile("cp.async.wait_group 1;\n");
        else
            asm volatile("cp.async.wait_group 0;\n");
        __syncthreads();   // bar A: buffer g ready; buffer (g+2)%3 free; sv2 ready

        // ---- prefetch batch g+2 ----
        if (g + 2 < GB) {
            const float* hb = h + base + (size_t)(g + 2) * 4096;
            uint32_t sb = (uint32_t)__cvta_generic_to_shared(
                              &shbase[((g + 2) % NBUF) * 4096]);
#pragma unroll
            for (int c = tid; c < 1024; c += 128) {
                int row = c >> 4, q = c & 15;
                int slot = q ^ ((row & 1) << 2);
                cp_async16(sb + row * 256 + slot * 16, hb + c * 4);
            }
            asm volatile("cp.async.commit_group;\n");
        }

        const float* shb = &shbase[(g % NBUF) * 4096];

        // ---- per-q: load frags (swizzled LDS.128), dots, convert to half2 ----
        unsigned ah0[4], ah1[4], ah2[4], ah3[4];
        float pd0 = 0.f, pd1 = 0.f;
#pragma unroll
        for (int q = 0; q < 4; ++q) {
            const int slot = (4 * q + tig) ^ swz;
            const float4 vA = *reinterpret_cast<const float4*>(&shb[rA * 64 + slot * 4]);
            const float4 vB = *reinterpret_cast<const float4*>(&shb[rB * 64 + slot * 4]);
            const float4 vv = *reinterpret_cast<const float4*>(&sv2[16 * q + 4 * tig]);

            pd0 = fmaf(vA.x, vv.x, fmaf(vA.y, vv.y,
                  fmaf(vA.z, vv.z, fmaf(vA.w, vv.w, pd0))));
            pd1 = fmaf(vB.x, vv.x, fmaf(vB.y, vv.y,
                  fmaf(vB.z, vv.z, fmaf(vB.w, vv.w, pd1))));

            ah0[q] = h2u(__floats2half2_rn(vA.x, vA.y));
            ah1[q] = h2u(__floats2half2_rn(vB.x, vB.y));
            ah2[q] = h2u(__floats2half2_rn(vA.z, vA.w));
            ah3[q] = h2u(__floats2half2_rn(vB.z, vB.w));
        }

        // ---- reduce dots over tig lanes; publish ----
        pd0 += __shfl_xor_sync(0xffffffffu, pd0, 1);
        pd0 += __shfl_xor_sync(0xffffffffu, pd0, 2);
        pd1 += __shfl_xor_sync(0xffffffffu, pd1, 1);
        pd1 += __shfl_xor_sync(0xffffffffu, pd1, 2);
        float* sd = sdots + (g & 1) * 64;
        if (tig == 0) { sd[rA] = pd0; sd[rB] = pd1; }
        __syncthreads();   // bar B: sdots complete

        // ---- warp-local softmax over rows 1..63 ----
        float x0 = (lane >= 1) ? sd[lane] : -1e30f;
        float x1 = sd[lane + 32];
        float m = fmaxf(x0, x1);
#pragma unroll
        for (int off = 16; off; off >>= 1)
            m = fmaxf(m, __shfl_xor_sync(0xffffffffu, m, off));
        float e0s = (lane >= 1) ? __expf(x0 - m) : 0.f;
        float e1s = __expf(x1 - m);
        float s = e0s + e1s;
#pragma unroll
        for (int off = 16; off; off >>= 1)
            s += __shfl_xor_sync(0xffffffffu, s, off);
        const float inv = 1.f / s;

        const float fA = (rA == 0) ? 1.f : __expf(pd0 - m) * inv;
        const float fB = __expf(pd1 - m) * inv;   // rB >= 8, never robot

        // ---- GEMM + epilogue in two nt-halves (acc = 16 regs) ----
        float* ob = out + base + (size_t)g * 4096;
#pragma unroll
        for (int hh = 0; hh < 2; ++hh) {
            float acc[4][4];
#pragma unroll
            for (int n2 = 0; n2 < 4; ++n2)
#pragma unroll
                for (int k = 0; k < 4; ++k) acc[n2][k] = 0.f;

#pragma unroll
            for (int q = 0; q < 4; ++q) {
#pragma unroll
                for (int n2 = 0; n2 < 4; ++n2) {
                    const int nt = hh * 4 + n2;
                    asm volatile(
                        "mma.sync.aligned.m16n8k16.row.col.f32.f16.f16.f32 "
                        "{%0,%1,%2,%3}, {%4,%5,%6,%7}, {%8,%9}, {%0,%1,%2,%3};"
                        : "+f"(acc[n2][0]), "+f"(acc[n2][1]),
                          "+f"(acc[n2][2]), "+f"(acc[n2][3])
                        : "r"(ah0[q]), "r"(ah1[q]), "r"(ah2[q]), "r"(ah3[q]),
                          "r"(bfr[q][nt][0]), "r"(bfr[q][nt][1]));
                }
            }

#pragma unroll
            for (int pp = 0; pp < 2; ++pp) {
                const int col = (hh * 2 + pp) * 16 + tig * 4;
                float4 v0 = make_float4(elu1(acc[2 * pp][0] * fA),
                                        elu1(acc[2 * pp][1] * fA),
                                        elu1(acc[2 * pp + 1][0] * fA),
                                        elu1(acc[2 * pp + 1][1] * fA));
                float4 v1 = make_float4(elu1(acc[2 * pp][2] * fB),
                                        elu1(acc[2 * pp][3] * fB),
                                        elu1(acc[2 * pp + 1][2] * fB),
                                        elu1(acc[2 * pp + 1][3] * fB));
                *reinterpret_cast<float4*>(ob + rA * 64 + col) = v0;
                *reinterpret_cast<float4*>(ob + rB * 64 + col) = v1;
            }
        }
    }
}

extern "C" void kernel_launch(void* const* d_in, const int* in_sizes, int n_in,
                              void* d_out, int out_size) {
    const float* h = (const float*)d_in[0];   // (16384, 64, 64) f32
    const float* W = (const float*)d_in[1];   // (64, 64) f32
    const float* a = (const float*)d_in[2];   // (128, 1) f32
    float* out = (float*)d_out;               // (16384, 64, 64) f32

    const int smem_bytes = SMEM_FLOATS * sizeof(float);   // ~49.9 KB
    cudaFuncSetAttribute(gat_fused_kernel,
                         cudaFuncAttributeMaxDynamicSharedMemorySize, smem_bytes);
    gat_fused_kernel<<<16384 / GB, 128, smem_bytes>>>(h, W, a, out);
}